// round 2
// baseline (speedup 1.0000x reference)
#include <cuda_runtime.h>
#include <math.h>

// Problem constants
#define M_BATCH   8192
#define N_NODES   1023
#define N_PAD     1024
#define K_DIM     1024
#define N_CLASSES 10
#define N_LEAVES  1024

// Scratch (allocation-free rule: __device__ globals)
__device__ float g_probs[(size_t)M_BATCH * N_PAD];   // sigmoid outputs, [m][n] layout
__device__ float g_leaf_reward[N_LEAVES];

// ---------------------------------------------------------------------------
// Kernel 1: leaf_reward[l] = softmax(leaf_dist[l,:]) . class_reward
// ---------------------------------------------------------------------------
__global__ void leaf_reward_kernel(const float* __restrict__ leaf_dist,
                                   const float* __restrict__ class_reward) {
    int l = blockIdx.x * blockDim.x + threadIdx.x;
    if (l >= N_LEAVES) return;
    float v[N_CLASSES];
    float mx = -1e30f;
#pragma unroll
    for (int c = 0; c < N_CLASSES; c++) {
        v[c] = leaf_dist[l * N_CLASSES + c];
        mx = fmaxf(mx, v[c]);
    }
    float s = 0.f;
#pragma unroll
    for (int c = 0; c < N_CLASSES; c++) {
        v[c] = expf(v[c] - mx);
        s += v[c];
    }
    float inv = 1.f / s;
    float r = 0.f;
#pragma unroll
    for (int c = 0; c < N_CLASSES; c++) r += v[c] * inv * class_reward[c];
    g_leaf_reward[l] = r;
}

// ---------------------------------------------------------------------------
// Kernel 2: tiled SGEMM (logits = x @ W^T) fused with sigmoid(beta*(z+b))
//   BM=128, BN=64, BK=16, 256 threads, each thread -> 8 (m) x 4 (n) outputs.
//   Thread n-columns are strided (n = tx + 16*j) so epilogue stores coalesce.
// ---------------------------------------------------------------------------
#define BM 128
#define BN 64
#define BK 16
#define TM 8
#define TN 4

__global__ __launch_bounds__(256, 2)
void gemm_sigmoid_kernel(const float* __restrict__ x,
                         const float* __restrict__ W,
                         const float* __restrict__ bvec,
                         const float* __restrict__ beta) {
    __shared__ float As[BK][BM];   // As[k][m]
    __shared__ float Bs[BK][BN];   // Bs[k][n]

    const int tid = threadIdx.x;
    const int tx  = tid & 15;      // n sub-index (0..15)
    const int ty  = tid >> 4;      // m sub-index (0..15)
    const int m0  = blockIdx.y * BM;
    const int n0  = blockIdx.x * BN;

    float acc[TM][TN];
#pragma unroll
    for (int i = 0; i < TM; i++)
#pragma unroll
        for (int j = 0; j < TN; j++) acc[i][j] = 0.f;

    for (int k0 = 0; k0 < K_DIM; k0 += BK) {
        // ---- load A tile: x[m0..m0+127][k0..k0+15]  (512 float4s, 2/thread)
#pragma unroll
        for (int u = 0; u < 2; u++) {
            int idx = tid + u * 256;
            int row = idx >> 2;           // 0..127
            int c4  = (idx & 3) * 4;      // 0,4,8,12
            float4 v = *reinterpret_cast<const float4*>(
                &x[(size_t)(m0 + row) * K_DIM + k0 + c4]);
            As[c4 + 0][row] = v.x;
            As[c4 + 1][row] = v.y;
            As[c4 + 2][row] = v.z;
            As[c4 + 3][row] = v.w;
        }
        // ---- load B tile: W[n0..n0+63][k0..k0+15] -> Bs[k][n] (transposed)
        {
            int row = tid >> 2;           // 0..63 (n within tile)
            int c4  = (tid & 3) * 4;      // 0,4,8,12
            int n   = n0 + row;
            float4 v = make_float4(0.f, 0.f, 0.f, 0.f);
            if (n < N_NODES)
                v = *reinterpret_cast<const float4*>(
                    &W[(size_t)n * K_DIM + k0 + c4]);
            Bs[c4 + 0][row] = v.x;
            Bs[c4 + 1][row] = v.y;
            Bs[c4 + 2][row] = v.z;
            Bs[c4 + 3][row] = v.w;
        }
        __syncthreads();

#pragma unroll
        for (int k = 0; k < BK; k++) {
            float a[TM], bb[TN];
            float4 a0 = *reinterpret_cast<const float4*>(&As[k][ty * TM]);
            float4 a1 = *reinterpret_cast<const float4*>(&As[k][ty * TM + 4]);
            a[0] = a0.x; a[1] = a0.y; a[2] = a0.z; a[3] = a0.w;
            a[4] = a1.x; a[5] = a1.y; a[6] = a1.z; a[7] = a1.w;
#pragma unroll
            for (int j = 0; j < TN; j++) bb[j] = Bs[k][tx + 16 * j];
#pragma unroll
            for (int i = 0; i < TM; i++)
#pragma unroll
                for (int j = 0; j < TN; j++)
                    acc[i][j] = fmaf(a[i], bb[j], acc[i][j]);
        }
        __syncthreads();
    }

    // ---- epilogue: sigmoid(beta*(z+b)), coalesced stores to g_probs[m][n]
#pragma unroll
    for (int j = 0; j < TN; j++) {
        int n = n0 + tx + 16 * j;
        if (n >= N_NODES) continue;
        float bn  = bvec[n];
        float btn = beta[n];
#pragma unroll
        for (int i = 0; i < TM; i++) {
            int m = m0 + ty * TM + i;
            float z = btn * (acc[i][j] + bn);
            g_probs[(size_t)m * N_PAD + n] = 1.f / (1.f + __expf(-z));
        }
    }
}

// ---------------------------------------------------------------------------
// Kernel 3: per-row bottom-up tree fold.
//   V[node] = p*V[2node+1] + (1-p)*V[2node+2]; loss = V[0].
//   Level-by-level in shared memory with ping-pong buffers.
// ---------------------------------------------------------------------------
__global__ __launch_bounds__(256)
void fold_kernel(float* __restrict__ out) {
    __shared__ float pr[N_NODES];
    __shared__ float Va[N_LEAVES];
    __shared__ float Vb[N_LEAVES / 2];

    const int row = blockIdx.x;
    const int tid = threadIdx.x;
    const float* p = &g_probs[(size_t)row * N_PAD];

    for (int i = tid; i < N_NODES; i += 256) pr[i] = p[i];
    for (int i = tid; i < N_LEAVES; i += 256) Va[i] = g_leaf_reward[i];
    __syncthreads();

    float* src = Va;
    float* dst = Vb;
    for (int k = 9; k >= 1; k--) {
        int cnt = 1 << k;
        int off = cnt - 1;
        for (int j = tid; j < cnt; j += 256) {
            float pp = pr[off + j];
            dst[j] = pp * src[2 * j] + (1.f - pp) * src[2 * j + 1];
        }
        __syncthreads();
        float* t = src; src = dst; dst = t;
    }
    if (tid == 0) {
        float pp = pr[0];
        out[row] = pp * src[0] + (1.f - pp) * src[1];
    }
}

// ---------------------------------------------------------------------------
// kernel_launch
//   inputs (metadata order): x, W, b, beta, leaf_dist, class_reward
//   output: loss [8192] float32
// ---------------------------------------------------------------------------
extern "C" void kernel_launch(void* const* d_in, const int* in_sizes, int n_in,
                              void* d_out, int out_size) {
    const float* x            = (const float*)d_in[0];
    const float* W            = (const float*)d_in[1];
    const float* b            = (const float*)d_in[2];
    const float* beta         = (const float*)d_in[3];
    const float* leaf_dist    = (const float*)d_in[4];
    const float* class_reward = (const float*)d_in[5];
    float* out = (float*)d_out;

    leaf_reward_kernel<<<(N_LEAVES + 127) / 128, 128>>>(leaf_dist, class_reward);

    dim3 grid(N_PAD / BN, M_BATCH / BM);   // 16 x 64
    gemm_sigmoid_kernel<<<grid, 256>>>(x, W, b, beta);

    fold_kernel<<<M_BATCH, 256>>>(out);
}

// round 3
// speedup vs baseline: 1.0009x; 1.0009x over previous
#include <cuda_runtime.h>
#include <math.h>

// Problem constants
#define M_BATCH   8192
#define N_NODES   1023
#define N_PAD     1024
#define K_DIM     1024
#define N_CLASSES 10
#define N_LEAVES  1024

// Scratch (allocation-free rule: __device__ globals)
__device__ float g_probs[(size_t)M_BATCH * N_PAD];   // sigmoid outputs, [m][n] layout
__device__ float g_leaf_reward[N_LEAVES];

// ---------------------------------------------------------------------------
// Kernel 1: leaf_reward[l] = softmax(leaf_dist[l,:]) . class_reward
// ---------------------------------------------------------------------------
__global__ void leaf_reward_kernel(const float* __restrict__ leaf_dist,
                                   const float* __restrict__ class_reward) {
    int l = blockIdx.x * blockDim.x + threadIdx.x;
    if (l >= N_LEAVES) return;
    float v[N_CLASSES];
    float mx = -1e30f;
#pragma unroll
    for (int c = 0; c < N_CLASSES; c++) {
        v[c] = leaf_dist[l * N_CLASSES + c];
        mx = fmaxf(mx, v[c]);
    }
    float s = 0.f;
#pragma unroll
    for (int c = 0; c < N_CLASSES; c++) {
        v[c] = expf(v[c] - mx);
        s += v[c];
    }
    float inv = 1.f / s;
    float r = 0.f;
#pragma unroll
    for (int c = 0; c < N_CLASSES; c++) r += v[c] * inv * class_reward[c];
    g_leaf_reward[l] = r;
}

// ---------------------------------------------------------------------------
// Kernel 2: tiled SGEMM (logits = x @ W^T) fused with sigmoid(beta*(z+b))
//   BM=128, BN=64, BK=16, 256 threads, each thread -> 8 (m) x 4 (n) outputs.
//   Thread n-columns are strided (n = tx + 16*j) so epilogue stores coalesce.
// ---------------------------------------------------------------------------
#define BM 128
#define BN 64
#define BK 16
#define TM 8
#define TN 4

__global__ __launch_bounds__(256, 2)
void gemm_sigmoid_kernel(const float* __restrict__ x,
                         const float* __restrict__ W,
                         const float* __restrict__ bvec,
                         const float* __restrict__ beta) {
    __shared__ float As[BK][BM];   // As[k][m]
    __shared__ float Bs[BK][BN];   // Bs[k][n]

    const int tid = threadIdx.x;
    const int tx  = tid & 15;      // n sub-index (0..15)
    const int ty  = tid >> 4;      // m sub-index (0..15)
    const int m0  = blockIdx.y * BM;
    const int n0  = blockIdx.x * BN;

    float acc[TM][TN];
#pragma unroll
    for (int i = 0; i < TM; i++)
#pragma unroll
        for (int j = 0; j < TN; j++) acc[i][j] = 0.f;

    for (int k0 = 0; k0 < K_DIM; k0 += BK) {
        // ---- load A tile: x[m0..m0+127][k0..k0+15]  (512 float4s, 2/thread)
#pragma unroll
        for (int u = 0; u < 2; u++) {
            int idx = tid + u * 256;
            int row = idx >> 2;           // 0..127
            int c4  = (idx & 3) * 4;      // 0,4,8,12
            float4 v = *reinterpret_cast<const float4*>(
                &x[(size_t)(m0 + row) * K_DIM + k0 + c4]);
            As[c4 + 0][row] = v.x;
            As[c4 + 1][row] = v.y;
            As[c4 + 2][row] = v.z;
            As[c4 + 3][row] = v.w;
        }
        // ---- load B tile: W[n0..n0+63][k0..k0+15] -> Bs[k][n] (transposed)
        {
            int row = tid >> 2;           // 0..63 (n within tile)
            int c4  = (tid & 3) * 4;      // 0,4,8,12
            int n   = n0 + row;
            float4 v = make_float4(0.f, 0.f, 0.f, 0.f);
            if (n < N_NODES)
                v = *reinterpret_cast<const float4*>(
                    &W[(size_t)n * K_DIM + k0 + c4]);
            Bs[c4 + 0][row] = v.x;
            Bs[c4 + 1][row] = v.y;
            Bs[c4 + 2][row] = v.z;
            Bs[c4 + 3][row] = v.w;
        }
        __syncthreads();

#pragma unroll
        for (int k = 0; k < BK; k++) {
            float a[TM], bb[TN];
            float4 a0 = *reinterpret_cast<const float4*>(&As[k][ty * TM]);
            float4 a1 = *reinterpret_cast<const float4*>(&As[k][ty * TM + 4]);
            a[0] = a0.x; a[1] = a0.y; a[2] = a0.z; a[3] = a0.w;
            a[4] = a1.x; a[5] = a1.y; a[6] = a1.z; a[7] = a1.w;
#pragma unroll
            for (int j = 0; j < TN; j++) bb[j] = Bs[k][tx + 16 * j];
#pragma unroll
            for (int i = 0; i < TM; i++)
#pragma unroll
                for (int j = 0; j < TN; j++)
                    acc[i][j] = fmaf(a[i], bb[j], acc[i][j]);
        }
        __syncthreads();
    }

    // ---- epilogue: sigmoid(beta*(z+b)), coalesced stores to g_probs[m][n]
#pragma unroll
    for (int j = 0; j < TN; j++) {
        int n = n0 + tx + 16 * j;
        if (n >= N_NODES) continue;
        float bn  = bvec[n];
        float btn = beta[n];
#pragma unroll
        for (int i = 0; i < TM; i++) {
            int m = m0 + ty * TM + i;
            float z = btn * (acc[i][j] + bn);
            g_probs[(size_t)m * N_PAD + n] = 1.f / (1.f + __expf(-z));
        }
    }
}

// ---------------------------------------------------------------------------
// Kernel 3: per-row bottom-up tree fold.
//   V[node] = p*V[2node+1] + (1-p)*V[2node+2]; loss = V[0].
//   Level-by-level in shared memory with ping-pong buffers.
// ---------------------------------------------------------------------------
__global__ __launch_bounds__(256)
void fold_kernel(float* __restrict__ out) {
    __shared__ float pr[N_NODES];
    __shared__ float Va[N_LEAVES];
    __shared__ float Vb[N_LEAVES / 2];

    const int row = blockIdx.x;
    const int tid = threadIdx.x;
    const float* p = &g_probs[(size_t)row * N_PAD];

    for (int i = tid; i < N_NODES; i += 256) pr[i] = p[i];
    for (int i = tid; i < N_LEAVES; i += 256) Va[i] = g_leaf_reward[i];
    __syncthreads();

    float* src = Va;
    float* dst = Vb;
    for (int k = 9; k >= 1; k--) {
        int cnt = 1 << k;
        int off = cnt - 1;
        for (int j = tid; j < cnt; j += 256) {
            float pp = pr[off + j];
            dst[j] = pp * src[2 * j] + (1.f - pp) * src[2 * j + 1];
        }
        __syncthreads();
        float* t = src; src = dst; dst = t;
    }
    if (tid == 0) {
        float pp = pr[0];
        out[row] = pp * src[0] + (1.f - pp) * src[1];
    }
}

// ---------------------------------------------------------------------------
// kernel_launch
//   inputs (metadata order): x, W, b, beta, leaf_dist, class_reward
//   output: loss [8192] float32
// ---------------------------------------------------------------------------
extern "C" void kernel_launch(void* const* d_in, const int* in_sizes, int n_in,
                              void* d_out, int out_size) {
    const float* x            = (const float*)d_in[0];
    const float* W            = (const float*)d_in[1];
    const float* b            = (const float*)d_in[2];
    const float* beta         = (const float*)d_in[3];
    const float* leaf_dist    = (const float*)d_in[4];
    const float* class_reward = (const float*)d_in[5];
    float* out = (float*)d_out;

    leaf_reward_kernel<<<(N_LEAVES + 127) / 128, 128>>>(leaf_dist, class_reward);

    dim3 grid(N_PAD / BN, M_BATCH / BM);   // 16 x 64
    gemm_sigmoid_kernel<<<grid, 256>>>(x, W, b, beta);

    fold_kernel<<<M_BATCH, 256>>>(out);
}

// round 5
// speedup vs baseline: 5.1185x; 5.1140x over previous
#include <cuda_runtime.h>
#include <cuda_bf16.h>
#include <stdint.h>
#include <math.h>

// ---------------------------------------------------------------- constants
#define M_BATCH   8192
#define N_NODES   1023
#define N_PAD     1024
#define K_DIM     1024
#define N_CLASSES 10
#define N_LEAVES  1024

// GEMM tiling
#define GBM 128
#define GBN 128
#define GBK 64                        // bf16 per K-chunk = 128B row
#define NCHUNK (K_DIM / GBK)          // 16
#define STAGES 3
#define TILE_B 16384                  // one 128x64 bf16 tile, bytes
#define STAGE_B (2 * TILE_B)          // A+B per stage
#define GEMM_SMEM (STAGES * STAGE_B)  // 98304

// ---------------------------------------------------------------- scratch
__device__ __nv_bfloat16 g_xb[(size_t)M_BATCH * K_DIM];   // 16 MB
__device__ __nv_bfloat16 g_wb[(size_t)N_PAD * K_DIM];     // 2 MB (row 1023 zero)
__device__ float g_probs[(size_t)M_BATCH * N_PAD];        // 32 MB
__device__ float g_leaf_reward[N_LEAVES];

// ---------------------------------------------------------------- helpers
__device__ __forceinline__ uint32_t s2u(const void* p) {
    uint32_t a;
    asm("{ .reg .u64 t; cvta.to.shared.u64 t, %1; cvt.u32.u64 %0, t; }"
        : "=r"(a) : "l"(p));
    return a;
}
// SW128 swizzle of (row*128 + c), c<128:  row*128 + (c ^ ((row&7)*16))
__device__ __forceinline__ uint32_t swz(uint32_t o) { return o ^ ((o >> 3) & 0x70); }

#define LDSM_X4(r0, r1, r2, r3, a)                                             \
    asm volatile("ldmatrix.sync.aligned.m8n8.x4.shared.b16 {%0,%1,%2,%3}, [%4];" \
        : "=r"(r0), "=r"(r1), "=r"(r2), "=r"(r3) : "r"(a))

#define MMA16816(c, a, b0, b1)                                                 \
    asm volatile("mma.sync.aligned.m16n8k16.row.col.f32.bf16.bf16.f32 "        \
        "{%0,%1,%2,%3}, {%4,%5,%6,%7}, {%8,%9}, {%0,%1,%2,%3};"                \
        : "+f"((c)[0]), "+f"((c)[1]), "+f"((c)[2]), "+f"((c)[3])               \
        : "r"((a)[0]), "r"((a)[1]), "r"((a)[2]), "r"((a)[3]),                  \
          "r"(b0), "r"(b1))

// ---------------------------------------------------------------------------
// Kernel 1: leaf_reward[l] = softmax(leaf_dist[l,:]) . class_reward
// ---------------------------------------------------------------------------
__global__ void leaf_reward_kernel(const float* __restrict__ leaf_dist,
                                   const float* __restrict__ class_reward) {
    int l = blockIdx.x * blockDim.x + threadIdx.x;
    if (l >= N_LEAVES) return;
    float v[N_CLASSES];
    float mx = -1e30f;
#pragma unroll
    for (int c = 0; c < N_CLASSES; c++) {
        v[c] = leaf_dist[l * N_CLASSES + c];
        mx = fmaxf(mx, v[c]);
    }
    float s = 0.f;
#pragma unroll
    for (int c = 0; c < N_CLASSES; c++) { v[c] = expf(v[c] - mx); s += v[c]; }
    float inv = 1.f / s, r = 0.f;
#pragma unroll
    for (int c = 0; c < N_CLASSES; c++) r += v[c] * inv * class_reward[c];
    g_leaf_reward[l] = r;
}

// ---------------------------------------------------------------------------
// Kernels 1b/1c: fp32 -> bf16 conversion of x and W (W padded to 1024 rows)
// ---------------------------------------------------------------------------
__global__ __launch_bounds__(256)
void convert_x_kernel(const float* __restrict__ x) {
    size_t i = ((size_t)blockIdx.x * 256 + threadIdx.x) * 4;
    float4 v = *reinterpret_cast<const float4*>(x + i);
    __nv_bfloat16* d = g_xb + i;
    d[0] = __float2bfloat16(v.x);
    d[1] = __float2bfloat16(v.y);
    d[2] = __float2bfloat16(v.z);
    d[3] = __float2bfloat16(v.w);
}

__global__ __launch_bounds__(256)
void convert_w_kernel(const float* __restrict__ W) {
    size_t i = ((size_t)blockIdx.x * 256 + threadIdx.x) * 4;
    int row = (int)(i >> 10);   // /1024
    __nv_bfloat16* d = g_wb + i;
    if (row < N_NODES) {
        float4 v = *reinterpret_cast<const float4*>(W + i);
        d[0] = __float2bfloat16(v.x);
        d[1] = __float2bfloat16(v.y);
        d[2] = __float2bfloat16(v.z);
        d[3] = __float2bfloat16(v.w);
    } else {
        d[0] = __float2bfloat16(0.f); d[1] = __float2bfloat16(0.f);
        d[2] = __float2bfloat16(0.f); d[3] = __float2bfloat16(0.f);
    }
}

// ---------------------------------------------------------------------------
// Kernel 2: bf16 warp-MMA GEMM (logits = x @ W^T) + fused sigmoid epilogue.
//   mma.sync.m16n8k16 (sm_80-portable -> HMMA on sm_100).
//   8 warps: 4(M) x 2(N); warp tile 32x64; 3-stage cp.async pipeline.
// ---------------------------------------------------------------------------
__global__ __launch_bounds__(256)
void gemm_bf16_kernel(const float* __restrict__ bvec,
                      const float* __restrict__ beta) {
    extern __shared__ char smem[];
    const uint32_t sb = s2u(smem);
    const int tid  = threadIdx.x;
    const int wid  = tid >> 5, lane = tid & 31;
    const int wm   = wid & 3;            // 0..3  -> 32 M-rows each
    const int wn   = wid >> 2;           // 0..1  -> 64 N-cols each
    const int m0   = blockIdx.y * GBM;
    const int n0   = blockIdx.x * GBN;

    const int g = lane >> 3;             // ldmatrix 8-thread group
    const int r = lane & 7;

    const __nv_bfloat16* ag = g_xb + (size_t)m0 * K_DIM;
    const __nv_bfloat16* bg = g_wb + (size_t)n0 * K_DIM;

    // ---- stage loader: 128x64 A + 128x64 B, swizzled, one commit group
#define LOAD_STAGE(ck) do {                                                    \
    uint32_t _st = sb + ((ck) % STAGES) * STAGE_B;                             \
    _Pragma("unroll")                                                          \
    for (int _u = 0; _u < 4; _u++) {                                           \
        int _c = tid + 256 * _u;                                               \
        int _row = _c >> 3, _seg = _c & 7;                                     \
        uint32_t _off = swz((uint32_t)(_row * 128 + _seg * 16));               \
        const void* _as = ag + (size_t)_row * K_DIM + (ck) * GBK + _seg * 8;   \
        const void* _bs = bg + (size_t)_row * K_DIM + (ck) * GBK + _seg * 8;   \
        asm volatile("cp.async.cg.shared.global [%0], [%1], 16;"               \
                     :: "r"(_st + _off), "l"(_as));                            \
        asm volatile("cp.async.cg.shared.global [%0], [%1], 16;"               \
                     :: "r"(_st + TILE_B + _off), "l"(_bs));                   \
    }                                                                          \
    asm volatile("cp.async.commit_group;" ::: "memory");                       \
} while (0)

    float acc[2][8][4];
#pragma unroll
    for (int i = 0; i < 2; i++)
#pragma unroll
        for (int j = 0; j < 8; j++)
#pragma unroll
            for (int c = 0; c < 4; c++) acc[i][j][c] = 0.f;

    // Per-thread ldmatrix address components (row, and per-row XOR constant).
    // A x4 tile (16x16): rows m, matrices {m0-7,k0-7},{m8-15,k0-7},{m0-7,k8-15},{m8-15,k8-15}
    const int a_row[2] = { wm * 32 + 0 * 16 + r + (g & 1) * 8,
                           wm * 32 + 1 * 16 + r + (g & 1) * 8 };
    const int a_kadd   = (g >> 1) * 16;
    // B x4 tile (k16 x n16): rows n, matrices {n0-7,k0-7},{n0-7,k8-15},{n8-15,k0-7},{n8-15,k8-15}
    const int b_kadd   = (g & 1) * 16;

    LOAD_STAGE(0);
    LOAD_STAGE(1);

    for (int it = 0; it < NCHUNK; it++) {
        if (it + 1 < NCHUNK) asm volatile("cp.async.wait_group 1;" ::: "memory");
        else                 asm volatile("cp.async.wait_group 0;" ::: "memory");
        __syncthreads();

        if (it + 2 < NCHUNK) LOAD_STAGE(it + 2);

        const uint32_t stA = sb + (it % STAGES) * STAGE_B;
        const uint32_t stB = stA + TILE_B;

#pragma unroll
        for (int s = 0; s < 4; s++) {            // 4 x k16 steps per chunk
            uint32_t a[2][4];
#pragma unroll
            for (int i = 0; i < 2; i++) {
                int row = a_row[i];
                uint32_t addr = stA + (uint32_t)(row * 128)
                              + (uint32_t)((s * 32 + a_kadd) ^ ((row & 7) * 16));
                LDSM_X4(a[i][0], a[i][1], a[i][2], a[i][3], addr);
            }
            uint32_t bf[8][2];
#pragma unroll
            for (int j = 0; j < 4; j++) {        // n16 groups
                int row = wn * 64 + j * 16 + r + (g >> 1) * 8;
                uint32_t addr = stB + (uint32_t)(row * 128)
                              + (uint32_t)((s * 32 + b_kadd) ^ ((row & 7) * 16));
                LDSM_X4(bf[2 * j][0], bf[2 * j][1], bf[2 * j + 1][0], bf[2 * j + 1][1], addr);
            }
#pragma unroll
            for (int i = 0; i < 2; i++)
#pragma unroll
                for (int j = 0; j < 8; j++)
                    MMA16816(acc[i][j], a[i], bf[j][0], bf[j][1]);
        }
    }
    __syncthreads();

    // ---- stage bias/beta (reuse stage-0 smem), then fused sigmoid stores
    float* bs = reinterpret_cast<float*>(smem);
    float* es = bs + 128;
    if (tid < 128) {
        int n = n0 + tid;
        bs[tid] = (n < N_NODES) ? bvec[n] : 0.f;
        es[tid] = (n < N_NODES) ? beta[n] : 0.f;
    }
    __syncthreads();

    const int qr = lane >> 2;          // 0..7
    const int qc = lane & 3;           // 0..3
#pragma unroll
    for (int i = 0; i < 2; i++) {
        int mA = m0 + wm * 32 + i * 16 + qr;
#pragma unroll
        for (int j = 0; j < 8; j++) {
            int nl = wn * 64 + j * 8 + 2 * qc;   // local col (pair)
            float b0 = bs[nl],     e0 = es[nl];
            float b1 = bs[nl + 1], e1 = es[nl + 1];
            float z0 = e0 * (acc[i][j][0] + b0);
            float z1 = e1 * (acc[i][j][1] + b1);
            float z2 = e0 * (acc[i][j][2] + b0);
            float z3 = e1 * (acc[i][j][3] + b1);
            float2 v0 = make_float2(1.f / (1.f + __expf(-z0)),
                                    1.f / (1.f + __expf(-z1)));
            float2 v1 = make_float2(1.f / (1.f + __expf(-z2)),
                                    1.f / (1.f + __expf(-z3)));
            *reinterpret_cast<float2*>(&g_probs[(size_t)mA * N_PAD + n0 + nl]) = v0;
            *reinterpret_cast<float2*>(&g_probs[(size_t)(mA + 8) * N_PAD + n0 + nl]) = v1;
        }
    }
}

// ---------------------------------------------------------------------------
// Kernel 3: per-row bottom-up tree fold
// ---------------------------------------------------------------------------
__global__ __launch_bounds__(256)
void fold_kernel(float* __restrict__ out) {
    __shared__ float pr[N_NODES];
    __shared__ float Va[N_LEAVES];
    __shared__ float Vb[N_LEAVES / 2];

    const int row = blockIdx.x;
    const int tid = threadIdx.x;
    const float* p = &g_probs[(size_t)row * N_PAD];

    for (int i = tid; i < N_NODES; i += 256) pr[i] = p[i];
    for (int i = tid; i < N_LEAVES; i += 256) Va[i] = g_leaf_reward[i];
    __syncthreads();

    float* src = Va;
    float* dst = Vb;
    for (int k = 9; k >= 1; k--) {
        int cnt = 1 << k;
        int off = cnt - 1;
        for (int j = tid; j < cnt; j += 256) {
            float pp = pr[off + j];
            dst[j] = pp * src[2 * j] + (1.f - pp) * src[2 * j + 1];
        }
        __syncthreads();
        float* t = src; src = dst; dst = t;
    }
    if (tid == 0) {
        float pp = pr[0];
        out[row] = pp * src[0] + (1.f - pp) * src[1];
    }
}

// ---------------------------------------------------------------------------
// kernel_launch: x, W, b, beta, leaf_dist, class_reward -> loss[8192]
// ---------------------------------------------------------------------------
extern "C" void kernel_launch(void* const* d_in, const int* in_sizes, int n_in,
                              void* d_out, int out_size) {
    const float* x            = (const float*)d_in[0];
    const float* W            = (const float*)d_in[1];
    const float* b            = (const float*)d_in[2];
    const float* beta         = (const float*)d_in[3];
    const float* leaf_dist    = (const float*)d_in[4];
    const float* class_reward = (const float*)d_in[5];
    float* out = (float*)d_out;

    cudaFuncSetAttribute(gemm_bf16_kernel,
                         cudaFuncAttributeMaxDynamicSharedMemorySize, GEMM_SMEM);

    leaf_reward_kernel<<<(N_LEAVES + 127) / 128, 128>>>(leaf_dist, class_reward);
    convert_x_kernel<<<(int)(((size_t)M_BATCH * K_DIM / 4) / 256), 256>>>(x);
    convert_w_kernel<<<(int)(((size_t)N_PAD * K_DIM / 4) / 256), 256>>>(W);

    dim3 grid(N_PAD / GBN, M_BATCH / GBM);   // 8 x 64
    gemm_bf16_kernel<<<grid, 256, GEMM_SMEM>>>(b, beta);

    fold_kernel<<<M_BATCH, 256>>>(out);
}

// round 6
// speedup vs baseline: 6.1051x; 1.1928x over previous
#include <cuda_runtime.h>
#include <cuda_bf16.h>
#include <cuda_fp16.h>
#include <stdint.h>
#include <math.h>

// ---------------------------------------------------------------- constants
#define M_BATCH   8192
#define N_NODES   1023
#define N_PAD     1024
#define K_DIM     1024
#define N_CLASSES 10
#define N_LEAVES  1024

// GEMM tiling
#define GBM 128
#define GBN 128
#define GBK 64                        // bf16 per K-chunk = 128B row
#define NCHUNK (K_DIM / GBK)          // 16
#define STAGES 3
#define TILE_B 16384                  // one 128x64 bf16 tile, bytes
#define STAGE_B (2 * TILE_B)          // A+B per stage
#define GEMM_SMEM (STAGES * STAGE_B)  // 98304

// prep kernel block ranges
#define PREP_X_BLOCKS 8192
#define PREP_W_BLOCKS 1024
#define PREP_L_BLOCKS 4
#define PREP_BLOCKS (PREP_X_BLOCKS + PREP_W_BLOCKS + PREP_L_BLOCKS)

// ---------------------------------------------------------------- scratch
__device__ __nv_bfloat16 g_xb[(size_t)M_BATCH * K_DIM];   // 16 MB
__device__ __nv_bfloat16 g_wb[(size_t)N_PAD * K_DIM];     // 2 MB (row 1023 zero)
__device__ __half g_probs[(size_t)M_BATCH * N_PAD];       // 16 MB (fp16 probs)
__device__ float g_leaf_reward[N_LEAVES];

// ---------------------------------------------------------------- helpers
__device__ __forceinline__ uint32_t s2u(const void* p) {
    uint32_t a;
    asm("{ .reg .u64 t; cvta.to.shared.u64 t, %1; cvt.u32.u64 %0, t; }"
        : "=r"(a) : "l"(p));
    return a;
}
// SW128 swizzle of (row*128 + c), c<128:  row*128 + (c ^ ((row&7)*16))
__device__ __forceinline__ uint32_t swz(uint32_t o) { return o ^ ((o >> 3) & 0x70); }

#define LDSM_X4(r0, r1, r2, r3, a)                                             \
    asm volatile("ldmatrix.sync.aligned.m8n8.x4.shared.b16 {%0,%1,%2,%3}, [%4];" \
        : "=r"(r0), "=r"(r1), "=r"(r2), "=r"(r3) : "r"(a))

#define MMA16816(c, a, b0, b1)                                                 \
    asm volatile("mma.sync.aligned.m16n8k16.row.col.f32.bf16.bf16.f32 "        \
        "{%0,%1,%2,%3}, {%4,%5,%6,%7}, {%8,%9}, {%0,%1,%2,%3};"                \
        : "+f"((c)[0]), "+f"((c)[1]), "+f"((c)[2]), "+f"((c)[3])               \
        : "r"((a)[0]), "r"((a)[1]), "r"((a)[2]), "r"((a)[3]),                  \
          "r"(b0), "r"(b1))

// ---------------------------------------------------------------------------
// Kernel 1: fused prep — convert x, convert+pad W, leaf_reward.
//   blocks [0, 8192): x fp32->bf16 (1024 elems each)
//   blocks [8192, 9216): W fp32->bf16, row 1023 zeroed
//   blocks [9216, 9220): leaf_reward = softmax(leaf_dist) . class_reward
// ---------------------------------------------------------------------------
__global__ __launch_bounds__(256)
void prep_kernel(const float* __restrict__ x,
                 const float* __restrict__ W,
                 const float* __restrict__ leaf_dist,
                 const float* __restrict__ class_reward) {
    int blk = blockIdx.x;
    if (blk < PREP_X_BLOCKS) {
        size_t i = ((size_t)blk * 256 + threadIdx.x) * 4;
        float4 v = *reinterpret_cast<const float4*>(x + i);
        __nv_bfloat16* d = g_xb + i;
        d[0] = __float2bfloat16(v.x);
        d[1] = __float2bfloat16(v.y);
        d[2] = __float2bfloat16(v.z);
        d[3] = __float2bfloat16(v.w);
    } else if (blk < PREP_X_BLOCKS + PREP_W_BLOCKS) {
        size_t i = ((size_t)(blk - PREP_X_BLOCKS) * 256 + threadIdx.x) * 4;
        int row = (int)(i >> 10);
        __nv_bfloat16* d = g_wb + i;
        if (row < N_NODES) {
            float4 v = *reinterpret_cast<const float4*>(W + i);
            d[0] = __float2bfloat16(v.x);
            d[1] = __float2bfloat16(v.y);
            d[2] = __float2bfloat16(v.z);
            d[3] = __float2bfloat16(v.w);
        } else {
            d[0] = __float2bfloat16(0.f); d[1] = __float2bfloat16(0.f);
            d[2] = __float2bfloat16(0.f); d[3] = __float2bfloat16(0.f);
        }
    } else {
        int l = (blk - PREP_X_BLOCKS - PREP_W_BLOCKS) * 256 + threadIdx.x;
        if (l >= N_LEAVES) return;
        float v[N_CLASSES];
        float mx = -1e30f;
#pragma unroll
        for (int c = 0; c < N_CLASSES; c++) {
            v[c] = leaf_dist[l * N_CLASSES + c];
            mx = fmaxf(mx, v[c]);
        }
        float s = 0.f;
#pragma unroll
        for (int c = 0; c < N_CLASSES; c++) { v[c] = expf(v[c] - mx); s += v[c]; }
        float inv = 1.f / s, r = 0.f;
#pragma unroll
        for (int c = 0; c < N_CLASSES; c++) r += v[c] * inv * class_reward[c];
        g_leaf_reward[l] = r;
    }
}

// ---------------------------------------------------------------------------
// Kernel 2: bf16 warp-MMA GEMM (logits = x @ W^T) + fused sigmoid epilogue.
//   mma.sync.m16n8k16; 8 warps 4(M)x2(N); warp tile 32x64; 3-stage cp.async.
//   Epilogue stores fp16 probs (half2).
// ---------------------------------------------------------------------------
__global__ __launch_bounds__(256)
void gemm_bf16_kernel(const float* __restrict__ bvec,
                      const float* __restrict__ beta) {
    extern __shared__ char smem[];
    const uint32_t sb = s2u(smem);
    const int tid  = threadIdx.x;
    const int wid  = tid >> 5, lane = tid & 31;
    const int wm   = wid & 3;            // 0..3  -> 32 M-rows each
    const int wn   = wid >> 2;           // 0..1  -> 64 N-cols each
    const int m0   = blockIdx.y * GBM;
    const int n0   = blockIdx.x * GBN;

    const int g = lane >> 3;             // ldmatrix 8-thread group
    const int r = lane & 7;

    const __nv_bfloat16* ag = g_xb + (size_t)m0 * K_DIM;
    const __nv_bfloat16* bg = g_wb + (size_t)n0 * K_DIM;

#define LOAD_STAGE(ck) do {                                                    \
    uint32_t _st = sb + ((ck) % STAGES) * STAGE_B;                             \
    _Pragma("unroll")                                                          \
    for (int _u = 0; _u < 4; _u++) {                                           \
        int _c = tid + 256 * _u;                                               \
        int _row = _c >> 3, _seg = _c & 7;                                     \
        uint32_t _off = swz((uint32_t)(_row * 128 + _seg * 16));               \
        const void* _as = ag + (size_t)_row * K_DIM + (ck) * GBK + _seg * 8;   \
        const void* _bs = bg + (size_t)_row * K_DIM + (ck) * GBK + _seg * 8;   \
        asm volatile("cp.async.cg.shared.global [%0], [%1], 16;"               \
                     :: "r"(_st + _off), "l"(_as));                            \
        asm volatile("cp.async.cg.shared.global [%0], [%1], 16;"               \
                     :: "r"(_st + TILE_B + _off), "l"(_bs));                   \
    }                                                                          \
    asm volatile("cp.async.commit_group;" ::: "memory");                       \
} while (0)

    float acc[2][8][4];
#pragma unroll
    for (int i = 0; i < 2; i++)
#pragma unroll
        for (int j = 0; j < 8; j++)
#pragma unroll
            for (int c = 0; c < 4; c++) acc[i][j][c] = 0.f;

    const int a_row[2] = { wm * 32 + 0 * 16 + r + (g & 1) * 8,
                           wm * 32 + 1 * 16 + r + (g & 1) * 8 };
    const int a_kadd   = (g >> 1) * 16;
    const int b_kadd   = (g & 1) * 16;

    LOAD_STAGE(0);
    LOAD_STAGE(1);

    for (int it = 0; it < NCHUNK; it++) {
        if (it + 1 < NCHUNK) asm volatile("cp.async.wait_group 1;" ::: "memory");
        else                 asm volatile("cp.async.wait_group 0;" ::: "memory");
        __syncthreads();

        if (it + 2 < NCHUNK) LOAD_STAGE(it + 2);

        const uint32_t stA = sb + (it % STAGES) * STAGE_B;
        const uint32_t stB = stA + TILE_B;

#pragma unroll
        for (int s = 0; s < 4; s++) {            // 4 x k16 steps per chunk
            uint32_t a[2][4];
#pragma unroll
            for (int i = 0; i < 2; i++) {
                int row = a_row[i];
                uint32_t addr = stA + (uint32_t)(row * 128)
                              + (uint32_t)((s * 32 + a_kadd) ^ ((row & 7) * 16));
                LDSM_X4(a[i][0], a[i][1], a[i][2], a[i][3], addr);
            }
            uint32_t bf[8][2];
#pragma unroll
            for (int j = 0; j < 4; j++) {        // n16 groups
                int row = wn * 64 + j * 16 + r + (g >> 1) * 8;
                uint32_t addr = stB + (uint32_t)(row * 128)
                              + (uint32_t)((s * 32 + b_kadd) ^ ((row & 7) * 16));
                LDSM_X4(bf[2 * j][0], bf[2 * j][1], bf[2 * j + 1][0], bf[2 * j + 1][1], addr);
            }
#pragma unroll
            for (int i = 0; i < 2; i++)
#pragma unroll
                for (int j = 0; j < 8; j++)
                    MMA16816(acc[i][j], a[i], bf[j][0], bf[j][1]);
        }
    }
    __syncthreads();

    // ---- stage bias/beta (reuse stage-0 smem), then fused sigmoid + fp16 store
    float* bs = reinterpret_cast<float*>(smem);
    float* es = bs + 128;
    if (tid < 128) {
        int n = n0 + tid;
        bs[tid] = (n < N_NODES) ? bvec[n] : 0.f;
        es[tid] = (n < N_NODES) ? beta[n] : 0.f;
    }
    __syncthreads();

    const int qr = lane >> 2;          // 0..7
    const int qc = lane & 3;           // 0..3
#pragma unroll
    for (int i = 0; i < 2; i++) {
        int mA = m0 + wm * 32 + i * 16 + qr;
#pragma unroll
        for (int j = 0; j < 8; j++) {
            int nl = wn * 64 + j * 8 + 2 * qc;   // local col (pair)
            float b0 = bs[nl],     e0 = es[nl];
            float b1 = bs[nl + 1], e1 = es[nl + 1];
            float z0 = e0 * (acc[i][j][0] + b0);
            float z1 = e1 * (acc[i][j][1] + b1);
            float z2 = e0 * (acc[i][j][2] + b0);
            float z3 = e1 * (acc[i][j][3] + b1);
            __half2 v0 = __floats2half2_rn(1.f / (1.f + __expf(-z0)),
                                           1.f / (1.f + __expf(-z1)));
            __half2 v1 = __floats2half2_rn(1.f / (1.f + __expf(-z2)),
                                           1.f / (1.f + __expf(-z3)));
            *reinterpret_cast<__half2*>(&g_probs[(size_t)mA * N_PAD + n0 + nl]) = v0;
            *reinterpret_cast<__half2*>(&g_probs[(size_t)(mA + 8) * N_PAD + n0 + nl]) = v1;
        }
    }
}

// ---------------------------------------------------------------------------
// Kernel 3: warp-per-row tree fold.
//   Thread t owns leaves [32t, 32t+32): folds 5 levels locally (v at node 31+t),
//   then 5 shuffle rounds over nodes 0..30. Leaf rewards staged in padded smem.
// ---------------------------------------------------------------------------
#define FOLD_ROWS 8   // rows per 256-thread block
__device__ __forceinline__ int lpad(int i) { return i + (i >> 5); }

__global__ __launch_bounds__(256)
void fold_kernel(float* __restrict__ out) {
    __shared__ float Lr[N_LEAVES + N_LEAVES / 32];   // stride-33 padded

    const int tid  = threadIdx.x;
    const int wrp  = tid >> 5;
    const int lane = tid & 31;
    const int row  = blockIdx.x * FOLD_ROWS + wrp;

    // stage leaf rewards (conflict-free reads later via padding)
    for (int i = tid; i < N_LEAVES; i += 256) Lr[lpad(i)] = g_leaf_reward[i];
    __syncthreads();

    const __half* p = g_probs + (size_t)row * N_PAD;

    // local fold: leaves 32t..32t+31 -> V(node 31+t)
    float v[16];
    {
        const int base9 = 511 + 16 * lane;   // level-9 nodes
#pragma unroll
        for (int i = 0; i < 16; i++) {
            float pp = __half2float(__ldg(p + base9 + i));
            float l0 = Lr[lpad(32 * lane + 2 * i)];
            float l1 = Lr[lpad(32 * lane + 2 * i + 1)];
            v[i] = pp * l0 + (1.f - pp) * l1;
        }
        const int base8 = 255 + 8 * lane;
#pragma unroll
        for (int i = 0; i < 8; i++) {
            float pp = __half2float(__ldg(p + base8 + i));
            v[i] = pp * v[2 * i] + (1.f - pp) * v[2 * i + 1];
        }
        const int base7 = 127 + 4 * lane;
#pragma unroll
        for (int i = 0; i < 4; i++) {
            float pp = __half2float(__ldg(p + base7 + i));
            v[i] = pp * v[2 * i] + (1.f - pp) * v[2 * i + 1];
        }
        const int base6 = 63 + 2 * lane;
#pragma unroll
        for (int i = 0; i < 2; i++) {
            float pp = __half2float(__ldg(p + base6 + i));
            v[i] = pp * v[2 * i] + (1.f - pp) * v[2 * i + 1];
        }
        float pp = __half2float(__ldg(p + 31 + lane));
        v[0] = pp * v[0] + (1.f - pp) * v[1];
    }

    // shuffle fold over levels 4..0 (nodes 0..30)
    float vv = v[0];
#pragma unroll
    for (int lvl = 4; lvl >= 0; lvl--) {
        int cnt = 1 << lvl;
        float vl = __shfl_sync(0xFFFFFFFFu, vv, 2 * lane);
        float vr = __shfl_sync(0xFFFFFFFFu, vv, 2 * lane + 1);
        float pp = (lane < cnt) ? __half2float(__ldg(p + cnt - 1 + lane)) : 0.f;
        vv = pp * vl + (1.f - pp) * vr;
    }
    if (lane == 0) out[row] = vv;
}

// ---------------------------------------------------------------------------
// kernel_launch: x, W, b, beta, leaf_dist, class_reward -> loss[8192]
// ---------------------------------------------------------------------------
extern "C" void kernel_launch(void* const* d_in, const int* in_sizes, int n_in,
                              void* d_out, int out_size) {
    const float* x            = (const float*)d_in[0];
    const float* W            = (const float*)d_in[1];
    const float* b            = (const float*)d_in[2];
    const float* beta         = (const float*)d_in[3];
    const float* leaf_dist    = (const float*)d_in[4];
    const float* class_reward = (const float*)d_in[5];
    float* out = (float*)d_out;

    cudaFuncSetAttribute(gemm_bf16_kernel,
                         cudaFuncAttributeMaxDynamicSharedMemorySize, GEMM_SMEM);

    prep_kernel<<<PREP_BLOCKS, 256>>>(x, W, leaf_dist, class_reward);

    dim3 grid(N_PAD / GBN, M_BATCH / GBM);   // 8 x 64
    gemm_bf16_kernel<<<grid, 256, GEMM_SMEM>>>(b, beta);

    fold_kernel<<<M_BATCH / FOLD_ROWS, 256>>>(out);
}